// round 10
// baseline (speedup 1.0000x reference)
#include <cuda_runtime.h>

typedef unsigned long long u64;

#define H_      51
#define TSTEPS  512
#define BTOT    1024
#define NB      8
#define NBLK    (BTOT / NB)        // 128
#define NTHR    512
#define GP      224                // padded gate slots, permuted s = 4u+q
#define HROW    108                // per-batch h row: h1[0:51], pad, h2[52:103], pad
#define HC      27                 // ulonglong2 chunks per h row
#define LROW    896                // partial level row: 4 batches x 224

// ---- shared memory layout (float offsets) ----
#define OFF_W1   0                          // [13][224] 16B-chunks
#define OFF_W2   (OFF_W1 + 13*GP*4)         // [26][224]
#define OFF_XS   (OFF_W2 + 26*GP*4)         // [512][8]
#define OFF_HS   (OFF_XS + TSTEPS*8)        // 2 halves x [4][108]
#define OFF_C1   (OFF_HS + 2*4*HROW)        // 2 x [4][52]
#define OFF_C2   (OFF_C1 + 2*4*52)
#define OFF_PB1  (OFF_C2 + 2*4*52)          // 2 halves x 2 levels x [4][224]
#define OFF_PB2  (OFF_PB1 + 2*2*LROW)       // 2 halves x 3 levels x [4][224]
#define OFF_B1   (OFF_PB2 + 2*3*LROW)       // 224
#define OFF_B2   (OFF_B1 + GP)              // 224
#define OFF_WI1  (OFF_B2 + GP)              // 224
#define OFF_WL   (OFF_WI1 + GP)             // 56
#define OFF_BL   (OFF_WL + 56)              // 4
#define SMEM_FLOATS (OFF_BL + 4)
#define SMEM_BYTES  (SMEM_FLOATS * 4)       // ~197 KB

__device__ __forceinline__ void ffma2(u64 &d, u64 a, u64 b) {
    asm("fma.rn.f32x2 %0, %1, %2, %0;" : "+l"(d) : "l"(a), "l"(b));
}
__device__ __forceinline__ float2 unpk(u64 v) {
    float2 r;
    asm("mov.b64 {%0, %1}, %2;" : "=f"(r.x), "=f"(r.y) : "l"(v));
    return r;
}
__device__ __forceinline__ float sigf(float x) {
    return __fdividef(1.0f, 1.0f + __expf(-x));
}
__device__ __forceinline__ float tanhfast(float x) {
    return __fdividef(2.0f, 1.0f + __expf(-2.0f * x)) - 1.0f;
}
__device__ __forceinline__ void half_bar(int half) {
    asm volatile("bar.sync %0, %1;" :: "r"(1 + half), "r"(256) : "memory");
}

// k-paired gate GEMV (R6-proven shape): lane = gate slot col, NJ j-groups,
// 4 batches of this half. w: LDS.128 unique per lane; h: LDS.128 broadcast.
template<int NKQ, int NJ>
__device__ __forceinline__ void gate_gemv(const ulonglong2* __restrict__ wp,
                                          const ulonglong2* __restrict__ hp,
                                          u64 (&acc)[NJ][4])
{
#pragma unroll
    for (int j = 0; j < NJ; j++)
#pragma unroll
        for (int b = 0; b < 4; b++) acc[j][b] = 0ull;
#pragma unroll
    for (int i = 0; i < NKQ; i++) {
        ulonglong2 h[4];
#pragma unroll
        for (int b = 0; b < 4; b++) h[b] = hp[b * HC + i];
#pragma unroll
        for (int j = 0; j < NJ; j++) {
            ulonglong2 w = wp[i * GP + 32 * j];
#pragma unroll
            for (int b = 0; b < 4; b++) {
                ffma2(acc[j][b], w.x, h[b].x);
                ffma2(acc[j][b], w.y, h[b].y);
            }
        }
    }
}

template<int NJ, bool ADDX>
__device__ __forceinline__ void store_partial(float* __restrict__ pb,
                                              const float* __restrict__ wiP,
                                              u64 (&acc)[NJ][4],
                                              const float* __restrict__ xrow)
{
    float wi[NJ];
    if (ADDX) {
#pragma unroll
        for (int j = 0; j < NJ; j++) wi[j] = wiP[32 * j];
    }
#pragma unroll
    for (int b = 0; b < 4; b++) {
        float xv = ADDX ? xrow[b] : 0.0f;
#pragma unroll
        for (int j = 0; j < NJ; j++) {
            float2 p = unpk(acc[j][b]);
            float gv = p.x + p.y;
            if (ADDX) gv = fmaf(xv, wi[j], gv);
            pb[b * GP + 32 * j] = gv;
        }
    }
}

// pointwise update for one half: thread (b = (tid&255)>>6, u = tid&63).
// Level counts are warp-uniform: u<32 (jA slots): L1 2 / L2 3; u>=32: 1 / 2.
__device__ __forceinline__ void cell_update(float* sm, int half, int b, int u,
                                            bool act, bool doU2, bool doU1)
{
    if (!act) return;
    const bool hi = (u < 32);
    const int hsb = OFF_HS + half * 4 * HROW + b * HROW;
    if (doU2) {
        const float* pb = sm + OFF_PB2 + half * 3 * LROW + b * GP + 4 * u;
        float4 g = *(const float4*)(sm + OFF_B2 + 4 * u);
        {
            float4 p = *(const float4*)pb;
            g.x += p.x; g.y += p.y; g.z += p.z; g.w += p.w;
        }
        {
            float4 p = *(const float4*)(pb + LROW);
            g.x += p.x; g.y += p.y; g.z += p.z; g.w += p.w;
        }
        if (hi) {
            float4 p = *(const float4*)(pb + 2 * LROW);
            g.x += p.x; g.y += p.y; g.z += p.z; g.w += p.w;
        }
        float c  = sm[OFF_C2 + half * 208 + b * 52 + u];
        float cn = sigf(g.y) * c + sigf(g.x) * tanhfast(g.z);
        float hn = sigf(g.w) * tanhfast(cn);
        sm[OFF_C2 + half * 208 + b * 52 + u] = cn;
        sm[hsb + 52 + u] = hn;
    }
    if (doU1) {
        const float* pb = sm + OFF_PB1 + half * 2 * LROW + b * GP + 4 * u;
        float4 g = *(const float4*)(sm + OFF_B1 + 4 * u);
        {
            float4 p = *(const float4*)pb;
            g.x += p.x; g.y += p.y; g.z += p.z; g.w += p.w;
        }
        if (hi) {
            float4 p = *(const float4*)(pb + LROW);
            g.x += p.x; g.y += p.y; g.z += p.z; g.w += p.w;
        }
        float c  = sm[OFF_C1 + half * 208 + b * 52 + u];
        float cn = sigf(g.y) * c + sigf(g.x) * tanhfast(g.z);
        float hn = sigf(g.w) * tanhfast(cn);
        sm[OFF_C1 + half * 208 + b * 52 + u] = cn;
        sm[hsb + u] = hn;
    }
}

// output dot for this half's 4 batches: ob = lane&3, part = lane>>2 (8 x 7 k)
__device__ __forceinline__ void out_phase(const float* sm, int half, int lane,
                                          int bid, int tcol,
                                          float* __restrict__ out)
{
    int ob = lane & 3, part = lane >> 2;
    const float* h2 = sm + OFF_HS + half * 4 * HROW + ob * HROW + 52;
    float a = 0.0f;
#pragma unroll
    for (int kk = 0; kk < 7; kk++) {
        int k = part * 7 + kk;                     // k up to 55 -> zero pads
        a = fmaf(h2[k], sm[OFF_WL + k], a);
    }
    a += __shfl_xor_sync(0xffffffffu, a, 4);
    a += __shfl_xor_sync(0xffffffffu, a, 8);
    a += __shfl_xor_sync(0xffffffffu, a, 16);
    if (lane < 4)
        out[(bid * NB + half * 4 + ob) * TSTEPS + tcol] = a + sm[OFF_BL];
}

__global__ void __launch_bounds__(NTHR, 1)
lstm_kernel(const float* __restrict__ input,
            const float* __restrict__ Wih1, const float* __restrict__ Whh1,
            const float* __restrict__ bih1, const float* __restrict__ bhh1,
            const float* __restrict__ Wih2, const float* __restrict__ Whh2,
            const float* __restrict__ bih2, const float* __restrict__ bhh2,
            const float* __restrict__ Wlin, const float* __restrict__ blin,
            float* __restrict__ out)
{
    extern __shared__ float sm[];
    const int tid  = threadIdx.x;
    const int bid  = blockIdx.x;
    const int lane = tid & 31;
    const int wid  = tid >> 5;            // 0..15
    const int half = wid >> 3;            // 0/1
    const int lw   = wid & 7;             // local warp 0..7

    // ---- staging (slot s = 4u+q; original gate row og = q*51+u) ----
    for (int i = tid; i < 2 * 4 * HROW; i += NTHR) sm[OFF_HS + i] = 0.0f;
    for (int i = tid; i < 2 * 4 * 52 * 2; i += NTHR) sm[OFF_C1 + i] = 0.0f;
    for (int i = tid; i < TSTEPS * 8; i += NTHR) {
        int t = i >> 3, bb = i & 7;
        sm[OFF_XS + i] = input[t * BTOT + bid * NB + bb];
    }
    for (int i = tid; i < 13 * GP * 4; i += NTHR) {
        int c = i & 3, s = (i >> 2) % GP, kq = i / (GP * 4);
        int u = s >> 2, q = s & 3, k = 4 * kq + c;
        float v = 0.0f;
        if (u < H_ && k < H_) v = Whh1[(q * H_ + u) * H_ + k];
        sm[OFF_W1 + i] = v;
    }
    for (int i = tid; i < 26 * GP * 4; i += NTHR) {
        int c = i & 3, s = (i >> 2) % GP, kq = i / (GP * 4);
        int u = s >> 2, q = s & 3, k = 4 * kq + c;
        float v = 0.0f;
        if (u < H_) {
            if (k < H_)                  v = Wih2[(q * H_ + u) * H_ + k];
            else if (k >= 52 && k < 103) v = Whh2[(q * H_ + u) * H_ + (k - 52)];
        }
        sm[OFF_W2 + i] = v;
    }
    for (int i = tid; i < GP; i += NTHR) {
        int u = i >> 2, q = i & 3;
        float b1 = 0.0f, b2 = 0.0f, w1 = 0.0f;
        if (u < H_) {
            int og = q * H_ + u;
            b1 = bih1[og] + bhh1[og];
            b2 = bih2[og] + bhh2[og];
            w1 = Wih1[og];
        }
        sm[OFF_B1  + i] = b1;
        sm[OFF_B2  + i] = b2;
        sm[OFF_WI1 + i] = w1;
    }
    if (tid < 56) sm[OFF_WL + tid] = (tid < H_) ? Wlin[tid] : 0.0f;
    if (tid == 0) sm[OFF_BL] = blin[0];
    __syncthreads();

    // ---- per-warp role within half ----
    // lw0: L1 jA kq[0,7)  lvl0 +x   lw1: L1 jA kq[7,13) lvl1 (+out duty)
    // lw2: L1 jB kq[0,13) lvl0 +x
    // lw3: L2 jA kq[0,9) lvl0   lw4: L2 jA [9,18) lvl1   lw5: L2 jA [18,26) lvl2
    // lw6: L2 jB kq[0,13) lvl0  lw7: L2 jB [13,26) lvl1
    const bool isL1 = (lw < 3);
    const int kstart_tab[8] = {0, 7, 0, 0, 9, 18, 0, 13};
    const int level_tab[8]  = {0, 1, 0, 0, 1, 2, 0, 1};
    const int kstart = kstart_tab[lw];
    const int level  = level_tab[lw];
    const int jbase  = (lw == 2 || lw >= 6) ? 4 : 0;

    const ulonglong2* __restrict__ wp =
        (const ulonglong2*)(sm + (isL1 ? OFF_W1 : OFF_W2))
        + kstart * GP + lane + 32 * jbase;
    const ulonglong2* __restrict__ hp =
        (const ulonglong2*)(sm + OFF_HS + half * 4 * HROW) + kstart;
    float* pb = sm + (isL1 ? OFF_PB1 + half * 2 * LROW
                           : OFF_PB2 + half * 3 * LROW)
                + level * LROW + lane + 32 * jbase;
    const float* wiP = sm + OFF_WI1 + lane + 32 * jbase;

    const int t_ = tid & 255;
    const int ub = t_ >> 6;               // batch within half 0..3
    const int uu = t_ & 63;
    const bool uact = (uu < H_);

    auto run_gemv = [&](const float* xrow) {
        if (lw == 0)      { u64 a[4][4]; gate_gemv< 7,4>(wp, hp, a); store_partial<4,true >(pb, wiP, a, xrow); }
        else if (lw == 1) { u64 a[4][4]; gate_gemv< 6,4>(wp, hp, a); store_partial<4,false>(pb, wiP, a, xrow); }
        else if (lw == 2) { u64 a[3][4]; gate_gemv<13,3>(wp, hp, a); store_partial<3,true >(pb, wiP, a, xrow); }
        else if (lw == 3) { u64 a[4][4]; gate_gemv< 9,4>(wp, hp, a); store_partial<4,false>(pb, wiP, a, xrow); }
        else if (lw == 4) { u64 a[4][4]; gate_gemv< 9,4>(wp, hp, a); store_partial<4,false>(pb, wiP, a, xrow); }
        else if (lw == 5) { u64 a[4][4]; gate_gemv< 8,4>(wp, hp, a); store_partial<4,false>(pb, wiP, a, xrow); }
        else if (lw == 6) { u64 a[3][4]; gate_gemv<13,3>(wp, hp, a); store_partial<3,false>(pb, wiP, a, xrow); }
        else              { u64 a[3][4]; gate_gemv<13,3>(wp, hp, a); store_partial<3,false>(pb, wiP, a, xrow); }
    };

    // ---- prologue: G1(0), U1(0) ----
    if (isL1) run_gemv(sm + OFF_XS + 0 * 8 + half * 4);
    half_bar(half);
    cell_update(sm, half, ub, uu, uact, false, true);
    half_bar(half);

    // ---- pipelined recurrence (per-half barriers only) ----
    for (int t = 0; t < TSTEPS; t++) {
        if (isL1) {
            if (t + 1 < TSTEPS)
                run_gemv(sm + OFF_XS + (t + 1) * 8 + half * 4);
            if (lw == 1 && t > 0) out_phase(sm, half, lane, bid, t - 1, out);
        } else {
            run_gemv(nullptr);
        }
        half_bar(half);
        cell_update(sm, half, ub, uu, uact, true, t + 1 < TSTEPS);
        half_bar(half);
    }

    // ---- epilogue ----
    if (lw == 1) out_phase(sm, half, lane, bid, TSTEPS - 1, out);
}

extern "C" void kernel_launch(void* const* d_in, const int* in_sizes, int n_in,
                              void* d_out, int out_size)
{
    const float* input = (const float*)d_in[0];
    const float* Wih1  = (const float*)d_in[1];
    const float* Whh1  = (const float*)d_in[2];
    const float* bih1  = (const float*)d_in[3];
    const float* bhh1  = (const float*)d_in[4];
    const float* Wih2  = (const float*)d_in[5];
    const float* Whh2  = (const float*)d_in[6];
    const float* bih2  = (const float*)d_in[7];
    const float* bhh2  = (const float*)d_in[8];
    const float* Wlin  = (const float*)d_in[9];
    const float* blin  = (const float*)d_in[10];
    float* out = (float*)d_out;

    static bool attr_set = false;
    if (!attr_set) {
        cudaFuncSetAttribute(lstm_kernel,
                             cudaFuncAttributeMaxDynamicSharedMemorySize,
                             SMEM_BYTES);
        attr_set = true;
    }
    lstm_kernel<<<NBLK, NTHR, SMEM_BYTES>>>(input, Wih1, Whh1, bih1, bhh1,
                                            Wih2, Whh2, bih2, bhh2,
                                            Wlin, blin, out);
}